// round 4
// baseline (speedup 1.0000x reference)
#include <cuda_runtime.h>
#include <cuda_bf16.h>
#include <cstdint>

// VQ cdist: out[n,k] = sqrt(max(||x_n||^2 + ||e_k||^2 - 2 x_n.e_k, 0))
// N=65536, K=1024, D=64.
//
// R4: 128x64 output tile per CTA (was 128x128) -> acc 32 regs/thread,
// ~75 total regs -> 3 CTAs/SM (occ 23.6% -> ~37.5%) to hide LDG/MUFU/STG
// latency. 256 threads, 8 warps as 4(M)x2(N), 32x32 warp tiles.
// mma.sync m16n8k16 bf16 cross term, exact fp32 norms, permuted-B smem
// placement for float4 stores. b-fragments consumed per-ldmatrix to keep
// live registers low.

#define BM 128
#define BN 64
#define PAD_LD 72   // bf16 elements per smem row (64 + 8 pad -> 144B rows)

__device__ __forceinline__ void ldsm_x4(uint32_t& r0, uint32_t& r1, uint32_t& r2, uint32_t& r3, uint32_t addr) {
    asm volatile("ldmatrix.sync.aligned.m8n8.x4.shared.b16 {%0,%1,%2,%3}, [%4];"
                 : "=r"(r0), "=r"(r1), "=r"(r2), "=r"(r3) : "r"(addr));
}

__device__ __forceinline__ void mma_bf16(float* c, const uint32_t* a, uint32_t b0, uint32_t b1) {
    asm volatile("mma.sync.aligned.m16n8k16.row.col.f32.bf16.bf16.f32 "
                 "{%0,%1,%2,%3}, {%4,%5,%6,%7}, {%8,%9}, {%0,%1,%2,%3};"
                 : "+f"(c[0]), "+f"(c[1]), "+f"(c[2]), "+f"(c[3])
                 : "r"(a[0]), "r"(a[1]), "r"(a[2]), "r"(a[3]), "r"(b0), "r"(b1));
}

// logical col l (within 16-group) -> physical smem slot, so that mma fragment
// ownership {2t, 2t+1, 2t+8, 2t+9} (phys) maps to logical {4t..4t+3}.
__device__ __forceinline__ int bperm(int l) {
    int t = l >> 2, j = l & 3;
    return 2 * t + (j & 1) + ((j >> 1) << 3);
}

__global__ __launch_bounds__(256, 3)
void vq_cdist_kernel(const float* __restrict__ X,   // [N, 64]
                     const float* __restrict__ E,   // [K, 64]
                     float* __restrict__ out,       // [N, K]
                     int Kdim) {
    __shared__ __align__(16) __nv_bfloat16 As[BM][PAD_LD];
    __shared__ __align__(16) __nv_bfloat16 Bs[BN][PAD_LD];
    __shared__ __align__(16) float xsq[BM];
    __shared__ __align__(16) float esq[BN];

    const int tid  = threadIdx.x;
    const int lane = tid & 31;
    const int wid  = tid >> 5;
    const int m0 = blockIdx.y * BM;
    const int n0 = blockIdx.x * BN;

    // ---- Load B tile first (smaller): warp-contiguous float4 + permutation ----
    {
        const float4* Ev = reinterpret_cast<const float4*>(E + (size_t)n0 * 64);
        #pragma unroll
        for (int i = 0; i < 4; i++) {                      // 64 rows * 16 f4 = 1024
            const int f    = tid + i * 256;
            const int lrow = f >> 4;                       // logical local col (0..63)
            const int c4   = f & 15;
            const int prow = (lrow & ~15) | bperm(lrow & 15);
            float4 v = Ev[f];
            float ss = v.x * v.x + v.y * v.y + v.z * v.z + v.w * v.w;
            __nv_bfloat162 p0 = __floats2bfloat162_rn(v.x, v.y);
            __nv_bfloat162 p1 = __floats2bfloat162_rn(v.z, v.w);
            uint2 pk;
            pk.x = *reinterpret_cast<uint32_t*>(&p0);
            pk.y = *reinterpret_cast<uint32_t*>(&p1);
            *reinterpret_cast<uint2*>(&Bs[prow][c4 * 4]) = pk;
            ss += __shfl_xor_sync(0xffffffffu, ss, 1);
            ss += __shfl_xor_sync(0xffffffffu, ss, 2);
            ss += __shfl_xor_sync(0xffffffffu, ss, 4);
            ss += __shfl_xor_sync(0xffffffffu, ss, 8);
            if ((lane & 15) == 0) esq[lrow] = ss;          // logical index
        }
    }
    // ---- Load A tile: warp-contiguous float4, fp32->bf16, exact norms ----
    {
        const float4* Xv = reinterpret_cast<const float4*>(X + (size_t)m0 * 64);
        #pragma unroll
        for (int i = 0; i < 8; i++) {                      // 128 rows * 16 f4 = 2048
            const int f   = tid + i * 256;
            const int row = f >> 4;
            const int c4  = f & 15;
            float4 v = Xv[f];
            float ss = v.x * v.x + v.y * v.y + v.z * v.z + v.w * v.w;
            __nv_bfloat162 p0 = __floats2bfloat162_rn(v.x, v.y);
            __nv_bfloat162 p1 = __floats2bfloat162_rn(v.z, v.w);
            uint2 pk;
            pk.x = *reinterpret_cast<uint32_t*>(&p0);
            pk.y = *reinterpret_cast<uint32_t*>(&p1);
            *reinterpret_cast<uint2*>(&As[row][c4 * 4]) = pk;
            ss += __shfl_xor_sync(0xffffffffu, ss, 1);
            ss += __shfl_xor_sync(0xffffffffu, ss, 2);
            ss += __shfl_xor_sync(0xffffffffu, ss, 4);
            ss += __shfl_xor_sync(0xffffffffu, ss, 8);
            if ((lane & 15) == 0) xsq[row] = ss;
        }
    }
    __syncthreads();

    // ---- Warp tiling: 4 warps along M (32 rows), 2 along N (32 cols) ----
    const int wm = (wid & 3) * 32;
    const int wn = (wid >> 2) * 32;

    float acc[2][4][4];
    #pragma unroll
    for (int mt = 0; mt < 2; mt++)
        #pragma unroll
        for (int nt = 0; nt < 4; nt++)
            #pragma unroll
            for (int i = 0; i < 4; i++) acc[mt][nt][i] = 0.f;

    const uint32_t a_base = (uint32_t)__cvta_generic_to_shared(&As[0][0]);
    const uint32_t b_base = (uint32_t)__cvta_generic_to_shared(&Bs[0][0]);

    #pragma unroll
    for (int ks = 0; ks < 4; ks++) {
        const int kc = ks * 16;

        uint32_t a_frag[2][4];
        #pragma unroll
        for (int mt = 0; mt < 2; mt++) {
            int r = wm + mt * 16 + (lane & 15);
            int c = kc + ((lane >> 4) << 3);
            uint32_t addr = a_base + (uint32_t)(r * PAD_LD + c) * 2u;
            ldsm_x4(a_frag[mt][0], a_frag[mt][1], a_frag[mt][2], a_frag[mt][3], addr);
        }

        #pragma unroll
        for (int np = 0; np < 2; np++) {  // each x4 covers two 8-col (physical) n-tiles
            int nr = wn + np * 16 + ((lane >> 4) & 1) * 8 + (lane & 7);
            int kk = kc + ((lane >> 3) & 1) * 8;
            uint32_t addr = b_base + (uint32_t)(nr * PAD_LD + kk) * 2u;
            uint32_t r0, r1, r2, r3;
            ldsm_x4(r0, r1, r2, r3, addr);
            #pragma unroll
            for (int mt = 0; mt < 2; mt++) {
                mma_bf16(acc[mt][np * 2],     a_frag[mt], r0, r1);
                mma_bf16(acc[mt][np * 2 + 1], a_frag[mt], r2, r3);
            }
        }
    }

    // ---- Epilogue: thread owns 4 contiguous logical cols per 16-group ----
    const int rb = wm + (lane >> 2);
    const int t4 = (lane & 3) * 4;
    #pragma unroll
    for (int mt = 0; mt < 2; mt++) {
        const int lr0 = rb + mt * 16;
        const int lr1 = lr0 + 8;
        const float xsa = xsq[lr0];
        const float xsb = xsq[lr1];
        float* o0 = out + (size_t)(m0 + lr0) * Kdim + n0 + wn;
        float* o1 = out + (size_t)(m0 + lr1) * Kdim + n0 + wn;
        #pragma unroll
        for (int q = 0; q < 2; q++) {
            const int c = q * 16 + t4;
            const float4 es = *reinterpret_cast<const float4*>(&esq[wn + c]);
            float4 v0, v1;
            v0.x = sqrtf(fmaxf(xsa + es.x - 2.0f * acc[mt][2*q][0],   0.f));
            v0.y = sqrtf(fmaxf(xsa + es.y - 2.0f * acc[mt][2*q][1],   0.f));
            v0.z = sqrtf(fmaxf(xsa + es.z - 2.0f * acc[mt][2*q+1][0], 0.f));
            v0.w = sqrtf(fmaxf(xsa + es.w - 2.0f * acc[mt][2*q+1][1], 0.f));
            v1.x = sqrtf(fmaxf(xsb + es.x - 2.0f * acc[mt][2*q][2],   0.f));
            v1.y = sqrtf(fmaxf(xsb + es.y - 2.0f * acc[mt][2*q][3],   0.f));
            v1.z = sqrtf(fmaxf(xsb + es.z - 2.0f * acc[mt][2*q+1][2], 0.f));
            v1.w = sqrtf(fmaxf(xsb + es.w - 2.0f * acc[mt][2*q+1][3], 0.f));
            *reinterpret_cast<float4*>(o0 + c) = v0;
            *reinterpret_cast<float4*>(o1 + c) = v1;
        }
    }
}

extern "C" void kernel_launch(void* const* d_in, const int* in_sizes, int n_in,
                              void* d_out, int out_size) {
    const float* X = (const float*)d_in[0];   // inputs [N, 64]
    const float* E = (const float*)d_in[1];   // embeddings [K, 64]
    float* out = (float*)d_out;               // [N, K] fp32

    const int N = in_sizes[0] / 64;
    const int K = in_sizes[1] / 64;

    // grid.x = n-tiles: consecutive CTAs share the same A row-block (L2 reuse)
    dim3 grid(K / BN, N / BM);
    vq_cdist_kernel<<<grid, 256>>>(X, E, out, K);
}

// round 6
// speedup vs baseline: 1.0913x; 1.0913x over previous
#include <cuda_runtime.h>
#include <cuda_bf16.h>
#include <cstdint>

// VQ cdist: out[n,k] = sqrt(max(||x_n||^2 + ||e_k||^2 - 2 x_n.e_k, 0))
// N=65536, K=1024, D=64.  (tcgen05 unavailable: harness compiles via
// compute_103 virtual arch -> arch-specific instrs rejected. mma.sync path.)
//
// R6: three kernels.
//  1) conv kernels: X,E fp32 -> bf16 __device__ globals + exact fp32 norms
//     (conversion/norms done ONCE instead of per-CTA).
//  2) main: cp.async 16B chunks -> SW128-swizzled smem (no LDG/cvt/STS chain),
//     swizzled ldmatrix, m16n8k16 bf16 mma, 32x64 warp tiles (6B/elem LDSM
//     floor), permuted-B placement -> float4 STG epilogue.

#define BM 128
#define BN 128
#define MAXN 65536
#define MAXK 1024

__device__ __nv_bfloat16 g_Xbf[MAXN * 64];
__device__ float         g_xsq[MAXN];
__device__ __nv_bfloat16 g_Ebf[MAXK * 64];
__device__ float         g_esq[MAXK];

#define SWZ(o) ((o) ^ (((o) >> 3) & 0x70))

__device__ __forceinline__ void ldsm_x4(uint32_t& r0, uint32_t& r1, uint32_t& r2, uint32_t& r3, uint32_t addr) {
    asm volatile("ldmatrix.sync.aligned.m8n8.x4.shared.b16 {%0,%1,%2,%3}, [%4];"
                 : "=r"(r0), "=r"(r1), "=r"(r2), "=r"(r3) : "r"(addr));
}

__device__ __forceinline__ void mma_bf16(float* c, const uint32_t* a, uint32_t b0, uint32_t b1) {
    asm volatile("mma.sync.aligned.m16n8k16.row.col.f32.bf16.bf16.f32 "
                 "{%0,%1,%2,%3}, {%4,%5,%6,%7}, {%8,%9}, {%0,%1,%2,%3};"
                 : "+f"(c[0]), "+f"(c[1]), "+f"(c[2]), "+f"(c[3])
                 : "r"(a[0]), "r"(a[1]), "r"(a[2]), "r"(a[3]), "r"(b0), "r"(b1));
}

__device__ __forceinline__ void cp16(uint32_t dst, const void* src) {
    asm volatile("cp.async.cg.shared.global [%0], [%1], 16;" :: "r"(dst), "l"(src) : "memory");
}

// logical col l (within 16-group) -> physical smem row, so that mma fragment
// ownership {2t, 2t+1, 2t+8, 2t+9} (phys) maps to logical {4t..4t+3}.
__device__ __forceinline__ int bperm(int l) {
    int t = l >> 2, j = l & 3;
    return 2 * t + (j & 1) + ((j >> 1) << 3);
}

// ---------------- prep: fp32 -> bf16 + exact fp32 row norms ----------------
__global__ __launch_bounds__(256)
void conv_kernel(const float* __restrict__ src, __nv_bfloat16* __restrict__ dst,
                 float* __restrict__ sq) {
    const int tid  = threadIdx.x;
    const int lane = tid & 31;
    const float4* sv = reinterpret_cast<const float4*>(src) + (size_t)blockIdx.x * 2048;
    __nv_bfloat16* drow = dst + (size_t)blockIdx.x * 128 * 64;
    float* sqrow = sq + (size_t)blockIdx.x * 128;
    #pragma unroll
    for (int i = 0; i < 8; i++) {
        const int f   = tid + i * 256;     // 2048 float4 per 128-row block
        const int row = f >> 4;
        const int c4  = f & 15;
        float4 v = sv[f];
        float ss = v.x * v.x + v.y * v.y + v.z * v.z + v.w * v.w;
        __nv_bfloat162 p0 = __floats2bfloat162_rn(v.x, v.y);
        __nv_bfloat162 p1 = __floats2bfloat162_rn(v.z, v.w);
        uint2 pk;
        pk.x = *reinterpret_cast<uint32_t*>(&p0);
        pk.y = *reinterpret_cast<uint32_t*>(&p1);
        *reinterpret_cast<uint2*>(drow + row * 64 + c4 * 4) = pk;
        ss += __shfl_xor_sync(0xffffffffu, ss, 1);
        ss += __shfl_xor_sync(0xffffffffu, ss, 2);
        ss += __shfl_xor_sync(0xffffffffu, ss, 4);
        ss += __shfl_xor_sync(0xffffffffu, ss, 8);
        if ((lane & 15) == 0) sqrow[row] = ss;
    }
}

// ---------------- main ----------------
__global__ __launch_bounds__(256, 2)
void vq_cdist_kernel(float* __restrict__ out, int Kdim) {
    __shared__ __align__(128) char As[BM * 128];   // bf16 SW128, 128B rows
    __shared__ __align__(128) char Bs[BN * 128];   // permuted rows, SW128
    __shared__ __align__(16) float xs_s[BM];
    __shared__ __align__(16) float es_s[BN];       // logical order

    const int tid  = threadIdx.x;
    const int lane = tid & 31;
    const int wid  = tid >> 5;
    const int m0 = blockIdx.y * BM;
    const int n0 = blockIdx.x * BN;

    const uint32_t a_base = (uint32_t)__cvta_generic_to_shared(As);
    const uint32_t b_base = (uint32_t)__cvta_generic_to_shared(Bs);

    // ---- async tile loads: 16B chunks, swizzled dst ----
    #pragma unroll
    for (int i = 0; i < 4; i++) {                  // A: 1024 chunks
        const int f   = tid + i * 256;
        const int row = f >> 3;                    // 8 chunks per row
        const int c   = f & 7;
        cp16(a_base + SWZ((uint32_t)(row * 128 + c * 16)),
             g_Xbf + (size_t)(m0 + row) * 64 + c * 8);
    }
    #pragma unroll
    for (int i = 0; i < 4; i++) {                  // B: 1024 chunks, permuted rows
        const int f    = tid + i * 256;
        const int lrow = f >> 3;
        const int c    = f & 7;
        const int prow = (lrow & ~15) | bperm(lrow & 15);
        cp16(b_base + SWZ((uint32_t)(prow * 128 + c * 16)),
             g_Ebf + (size_t)(n0 + lrow) * 64 + c * 8);
    }
    asm volatile("cp.async.commit_group;" ::: "memory");
    // norms (coalesced, 128 threads each)
    if (tid < 128) xs_s[tid] = g_xsq[m0 + tid];
    else           es_s[tid - 128] = g_esq[n0 + tid - 128];
    asm volatile("cp.async.wait_group 0;" ::: "memory");
    __syncthreads();

    // ---- warp tiling: 4 warps along M (32 rows), 2 along N (64 cols) ----
    const int wm = (wid & 3) * 32;
    const int wn = (wid >> 2) * 64;

    float acc[2][8][4];
    #pragma unroll
    for (int mt = 0; mt < 2; mt++)
        #pragma unroll
        for (int nt = 0; nt < 8; nt++)
            #pragma unroll
            for (int i = 0; i < 4; i++) acc[mt][nt][i] = 0.f;

    #pragma unroll
    for (int ks = 0; ks < 4; ks++) {
        const int kc = ks * 16;

        uint32_t a_frag[2][4];
        #pragma unroll
        for (int mt = 0; mt < 2; mt++) {
            const int r  = wm + mt * 16 + (lane & 15);
            const int cb = (kc + ((lane >> 4) << 3)) * 2;
            ldsm_x4(a_frag[mt][0], a_frag[mt][1], a_frag[mt][2], a_frag[mt][3],
                    a_base + SWZ((uint32_t)(r * 128 + cb)));
        }

        #pragma unroll
        for (int np = 0; np < 4; np++) {   // each x4 covers two 8-col physical n-tiles
            const int nr = wn + np * 16 + ((lane >> 4) & 1) * 8 + (lane & 7);
            const int kb = (kc + ((lane >> 3) & 1) * 8) * 2;
            uint32_t r0, r1, r2, r3;
            ldsm_x4(r0, r1, r2, r3, b_base + SWZ((uint32_t)(nr * 128 + kb)));
            #pragma unroll
            for (int mt = 0; mt < 2; mt++) {
                mma_bf16(acc[mt][np * 2],     a_frag[mt], r0, r1);
                mma_bf16(acc[mt][np * 2 + 1], a_frag[mt], r2, r3);
            }
        }
    }

    // ---- epilogue: thread owns 4 contiguous logical cols per 16-group ----
    const int rb = wm + (lane >> 2);
    const int t4 = (lane & 3) * 4;
    #pragma unroll
    for (int mt = 0; mt < 2; mt++) {
        const int lr0 = rb + mt * 16;
        const int lr1 = lr0 + 8;
        const float xsa = xs_s[lr0];
        const float xsb = xs_s[lr1];
        float* o0 = out + (size_t)(m0 + lr0) * Kdim + n0 + wn;
        float* o1 = out + (size_t)(m0 + lr1) * Kdim + n0 + wn;
        #pragma unroll
        for (int q = 0; q < 4; q++) {
            const int c = q * 16 + t4;
            const float4 es = *reinterpret_cast<const float4*>(&es_s[wn + c]);
            float4 v0, v1;
            v0.x = sqrtf(fmaxf(xsa + es.x - 2.0f * acc[mt][2*q][0],   0.f));
            v0.y = sqrtf(fmaxf(xsa + es.y - 2.0f * acc[mt][2*q][1],   0.f));
            v0.z = sqrtf(fmaxf(xsa + es.z - 2.0f * acc[mt][2*q+1][0], 0.f));
            v0.w = sqrtf(fmaxf(xsa + es.w - 2.0f * acc[mt][2*q+1][1], 0.f));
            v1.x = sqrtf(fmaxf(xsb + es.x - 2.0f * acc[mt][2*q][2],   0.f));
            v1.y = sqrtf(fmaxf(xsb + es.y - 2.0f * acc[mt][2*q][3],   0.f));
            v1.z = sqrtf(fmaxf(xsb + es.z - 2.0f * acc[mt][2*q+1][2], 0.f));
            v1.w = sqrtf(fmaxf(xsb + es.w - 2.0f * acc[mt][2*q+1][3], 0.f));
            *reinterpret_cast<float4*>(o0 + c) = v0;
            *reinterpret_cast<float4*>(o1 + c) = v1;
        }
    }
}

extern "C" void kernel_launch(void* const* d_in, const int* in_sizes, int n_in,
                              void* d_out, int out_size) {
    const float* X = (const float*)d_in[0];   // inputs [N, 64]
    const float* E = (const float*)d_in[1];   // embeddings [K, 64]
    float* out = (float*)d_out;               // [N, K] fp32

    const int N = in_sizes[0] / 64;
    const int K = in_sizes[1] / 64;

    __nv_bfloat16 *xbf_p, *ebf_p;
    float *xsq_p, *esq_p;
    cudaGetSymbolAddress((void**)&xbf_p, g_Xbf);
    cudaGetSymbolAddress((void**)&ebf_p, g_Ebf);
    cudaGetSymbolAddress((void**)&xsq_p, g_xsq);
    cudaGetSymbolAddress((void**)&esq_p, g_esq);

    conv_kernel<<<K / 128, 256>>>(E, ebf_p, esq_p);
    conv_kernel<<<N / 128, 256>>>(X, xbf_p, xsq_p);

    dim3 grid(K / BN, N / BM);
    vq_cdist_kernel<<<grid, 256>>>(out, K);
}

// round 7
// speedup vs baseline: 1.2457x; 1.1414x over previous
#include <cuda_runtime.h>
#include <cuda_bf16.h>
#include <cstdint>

// VQ cdist: out[n,k] = sqrt(max(||x_n||^2 + ||e_k||^2 - 2 x_n.e_k, 0))
// N=65536, K=1024, D=64.  mma.sync path (tcgen05 rejected by compute_103).
//
// R7:
//  1) ONE merged conv kernel (E+X blocks concurrent) -> bf16 globals + norms.
//  2) Persistent main kernel, 2 CTAs/SM, grid-stride over 128x128 tiles with a
//     2-stage cp.async pipeline: loads of tile t+stride overlap mma+epilogue
//     of tile t. 32x64 warp tiles (6B/elem LDSM floor), permuted-B placement
//     -> float4 STG epilogue.

#define BM 128
#define BN 128
#define MAXN 65536
#define MAXK 1024

// per-stage smem layout (bytes): A 0..16384, B 16384..32768, xs 32768..33280,
// es 33280..33792. stage size 33792 (128-aligned).
#define ST_B   16384
#define ST_XS  32768
#define ST_ES  33280
#define STAGE  33792
#define DYN_SMEM (2 * STAGE)

__device__ __nv_bfloat16 g_Xbf[MAXN * 64];
__device__ float         g_xsq[MAXN];
__device__ __nv_bfloat16 g_Ebf[MAXK * 64];
__device__ float         g_esq[MAXK];

#define SWZ(o) ((o) ^ (((o) >> 3) & 0x70))

__device__ __forceinline__ void ldsm_x4(uint32_t& r0, uint32_t& r1, uint32_t& r2, uint32_t& r3, uint32_t addr) {
    asm volatile("ldmatrix.sync.aligned.m8n8.x4.shared.b16 {%0,%1,%2,%3}, [%4];"
                 : "=r"(r0), "=r"(r1), "=r"(r2), "=r"(r3) : "r"(addr));
}

__device__ __forceinline__ void mma_bf16(float* c, const uint32_t* a, uint32_t b0, uint32_t b1) {
    asm volatile("mma.sync.aligned.m16n8k16.row.col.f32.bf16.bf16.f32 "
                 "{%0,%1,%2,%3}, {%4,%5,%6,%7}, {%8,%9}, {%0,%1,%2,%3};"
                 : "+f"(c[0]), "+f"(c[1]), "+f"(c[2]), "+f"(c[3])
                 : "r"(a[0]), "r"(a[1]), "r"(a[2]), "r"(a[3]), "r"(b0), "r"(b1));
}

__device__ __forceinline__ void cp16(uint32_t dst, const void* src) {
    asm volatile("cp.async.cg.shared.global [%0], [%1], 16;" :: "r"(dst), "l"(src) : "memory");
}

// logical col l (within 16-group) -> physical smem row, so that mma fragment
// ownership {2t, 2t+1, 2t+8, 2t+9} (phys) maps to logical {4t..4t+3}.
__device__ __forceinline__ int bperm(int l) {
    int t = l >> 2, j = l & 3;
    return 2 * t + (j & 1) + ((j >> 1) << 3);
}

// ---------------- merged prep: fp32 -> bf16 + exact fp32 row norms ----------------
__global__ __launch_bounds__(256)
void conv_all(const float* __restrict__ X, const float* __restrict__ E, int kblocks) {
    const int b    = blockIdx.x;
    const int tid  = threadIdx.x;
    const int lane = tid & 31;
    const float4* sv;
    __nv_bfloat16* drow;
    float* sqrow;
    if (b < kblocks) {
        sv    = reinterpret_cast<const float4*>(E) + (size_t)b * 2048;
        drow  = g_Ebf + (size_t)b * 8192;
        sqrow = g_esq + (size_t)b * 128;
    } else {
        const int c = b - kblocks;
        sv    = reinterpret_cast<const float4*>(X) + (size_t)c * 2048;
        drow  = g_Xbf + (size_t)c * 8192;
        sqrow = g_xsq + (size_t)c * 128;
    }
    #pragma unroll
    for (int i = 0; i < 8; i++) {
        const int f   = tid + i * 256;     // 2048 float4 per 128-row block
        const int row = f >> 4;
        const int c4  = f & 15;
        float4 v = sv[f];
        float ss = v.x * v.x + v.y * v.y + v.z * v.z + v.w * v.w;
        __nv_bfloat162 p0 = __floats2bfloat162_rn(v.x, v.y);
        __nv_bfloat162 p1 = __floats2bfloat162_rn(v.z, v.w);
        uint2 pk;
        pk.x = *reinterpret_cast<uint32_t*>(&p0);
        pk.y = *reinterpret_cast<uint32_t*>(&p1);
        *reinterpret_cast<uint2*>(drow + row * 64 + c4 * 4) = pk;
        ss += __shfl_xor_sync(0xffffffffu, ss, 1);
        ss += __shfl_xor_sync(0xffffffffu, ss, 2);
        ss += __shfl_xor_sync(0xffffffffu, ss, 4);
        ss += __shfl_xor_sync(0xffffffffu, ss, 8);
        if ((lane & 15) == 0) sqrow[row] = ss;
    }
}

// ---------------- main: persistent, 2-stage cp.async pipeline ----------------
__device__ __forceinline__ void issue_tile_loads(uint32_t stg_base, int m0, int n0, int tid) {
    const uint32_t a0 = stg_base;
    const uint32_t b0 = stg_base + ST_B;
    #pragma unroll
    for (int i = 0; i < 4; i++) {                  // A: 1024 chunks of 16B
        const int f   = tid + i * 256;
        const int row = f >> 3;
        const int c   = f & 7;
        cp16(a0 + SWZ((uint32_t)(row * 128 + c * 16)),
             g_Xbf + (size_t)(m0 + row) * 64 + c * 8);
    }
    #pragma unroll
    for (int i = 0; i < 4; i++) {                  // B: 1024 chunks, permuted rows
        const int f    = tid + i * 256;
        const int lrow = f >> 3;
        const int c    = f & 7;
        const int prow = (lrow & ~15) | bperm(lrow & 15);
        cp16(b0 + SWZ((uint32_t)(prow * 128 + c * 16)),
             g_Ebf + (size_t)(n0 + lrow) * 64 + c * 8);
    }
    if (tid < 32)       cp16(stg_base + ST_XS + tid * 16, g_xsq + m0 + tid * 4);
    else if (tid < 64)  cp16(stg_base + ST_ES + (tid - 32) * 16, g_esq + n0 + (tid - 32) * 4);
}

__global__ __launch_bounds__(256, 2)
void vq_cdist_kernel(float* __restrict__ out, int Kdim, int nt_total, int nx) {
    extern __shared__ char smem[];
    const uint32_t s_base = (uint32_t)__cvta_generic_to_shared(smem);

    const int tid  = threadIdx.x;
    const int lane = tid & 31;
    const int wid  = tid >> 5;
    const int wm = (wid & 3) * 32;
    const int wn = (wid >> 2) * 64;
    const int stride = gridDim.x;

    int t = blockIdx.x;
    if (t < nt_total) {
        issue_tile_loads(s_base, (t / nx) * BM, (t % nx) * BN, tid);
        asm volatile("cp.async.commit_group;" ::: "memory");
    }

    int pb = 0;
    for (; t < nt_total; t += stride, pb ^= 1) {
        const int tn = t + stride;
        if (tn < nt_total) {
            issue_tile_loads(s_base + (pb ^ 1) * STAGE, (tn / nx) * BM, (tn % nx) * BN, tid);
            asm volatile("cp.async.commit_group;" ::: "memory");
            asm volatile("cp.async.wait_group 1;" ::: "memory");
        } else {
            asm volatile("cp.async.wait_group 0;" ::: "memory");
        }
        __syncthreads();

        const uint32_t a_base = s_base + pb * STAGE;
        const uint32_t b_base = a_base + ST_B;
        const float* xs_s = reinterpret_cast<const float*>(smem + pb * STAGE + ST_XS);
        const float* es_s = reinterpret_cast<const float*>(smem + pb * STAGE + ST_ES);
        const int m0 = (t / nx) * BM;
        const int n0 = (t % nx) * BN;

        float acc[2][8][4];
        #pragma unroll
        for (int mt = 0; mt < 2; mt++)
            #pragma unroll
            for (int nt2 = 0; nt2 < 8; nt2++)
                #pragma unroll
                for (int i = 0; i < 4; i++) acc[mt][nt2][i] = 0.f;

        #pragma unroll
        for (int ks = 0; ks < 4; ks++) {
            const int kc = ks * 16;

            uint32_t a_frag[2][4];
            #pragma unroll
            for (int mt = 0; mt < 2; mt++) {
                const int r  = wm + mt * 16 + (lane & 15);
                const int cb = (kc + ((lane >> 4) << 3)) * 2;
                ldsm_x4(a_frag[mt][0], a_frag[mt][1], a_frag[mt][2], a_frag[mt][3],
                        a_base + SWZ((uint32_t)(r * 128 + cb)));
            }

            #pragma unroll
            for (int np = 0; np < 4; np++) {
                const int nr = wn + np * 16 + ((lane >> 4) & 1) * 8 + (lane & 7);
                const int kb = (kc + ((lane >> 3) & 1) * 8) * 2;
                uint32_t r0, r1, r2, r3;
                ldsm_x4(r0, r1, r2, r3, b_base + SWZ((uint32_t)(nr * 128 + kb)));
                #pragma unroll
                for (int mt = 0; mt < 2; mt++) {
                    mma_bf16(acc[mt][np * 2],     a_frag[mt], r0, r1);
                    mma_bf16(acc[mt][np * 2 + 1], a_frag[mt], r2, r3);
                }
            }
        }

        // epilogue: thread owns 4 contiguous logical cols per 16-group
        const int rb = wm + (lane >> 2);
        const int t4 = (lane & 3) * 4;
        #pragma unroll
        for (int mt = 0; mt < 2; mt++) {
            const int lr0 = rb + mt * 16;
            const int lr1 = lr0 + 8;
            const float xsa = xs_s[lr0];
            const float xsb = xs_s[lr1];
            float* o0 = out + (size_t)(m0 + lr0) * Kdim + n0 + wn;
            float* o1 = out + (size_t)(m0 + lr1) * Kdim + n0 + wn;
            #pragma unroll
            for (int q = 0; q < 4; q++) {
                const int c = q * 16 + t4;
                const float4 es = *reinterpret_cast<const float4*>(&es_s[wn + c]);
                float4 v0, v1;
                v0.x = sqrtf(fmaxf(xsa + es.x - 2.0f * acc[mt][2*q][0],   0.f));
                v0.y = sqrtf(fmaxf(xsa + es.y - 2.0f * acc[mt][2*q][1],   0.f));
                v0.z = sqrtf(fmaxf(xsa + es.z - 2.0f * acc[mt][2*q+1][0], 0.f));
                v0.w = sqrtf(fmaxf(xsa + es.w - 2.0f * acc[mt][2*q+1][1], 0.f));
                v1.x = sqrtf(fmaxf(xsb + es.x - 2.0f * acc[mt][2*q][2],   0.f));
                v1.y = sqrtf(fmaxf(xsb + es.y - 2.0f * acc[mt][2*q][3],   0.f));
                v1.z = sqrtf(fmaxf(xsb + es.z - 2.0f * acc[mt][2*q+1][2], 0.f));
                v1.w = sqrtf(fmaxf(xsb + es.w - 2.0f * acc[mt][2*q+1][3], 0.f));
                *reinterpret_cast<float4*>(o0 + c) = v0;
                *reinterpret_cast<float4*>(o1 + c) = v1;
            }
        }
        __syncthreads();   // all reads of stage pb done before next prefetch overwrites it
    }
}

extern "C" void kernel_launch(void* const* d_in, const int* in_sizes, int n_in,
                              void* d_out, int out_size) {
    const float* X = (const float*)d_in[0];   // inputs [N, 64]
    const float* E = (const float*)d_in[1];   // embeddings [K, 64]
    float* out = (float*)d_out;               // [N, K] fp32

    const int N = in_sizes[0] / 64;
    const int K = in_sizes[1] / 64;
    const int nx = K / BN;
    const int nt_total = (N / BM) * nx;

    static int configured = 0;
    if (!configured) {
        cudaFuncSetAttribute(vq_cdist_kernel,
                             cudaFuncAttributeMaxDynamicSharedMemorySize, DYN_SMEM);
        configured = 1;
    }

    int sms = 148;
    cudaDeviceGetAttribute(&sms, cudaDevAttrMultiProcessorCount, 0);

    conv_all<<<K / 128 + N / 128, 256>>>(X, E, K / 128);
    vq_cdist_kernel<<<2 * sms, 256, DYN_SMEM>>>(out, K, nt_total, nx);
}

// round 8
// speedup vs baseline: 1.7692x; 1.4203x over previous
#include <cuda_runtime.h>
#include <cuda_bf16.h>
#include <cstdint>

// VQ cdist: out[n,k] = sqrt(max(||x_n||^2 + ||e_k||^2 - 2 x_n.e_k, 0))
// N=65536, K=1024, D=64.  mma.sync path (tcgen05 rejected by compute_103).
//
// R8 (on top of R7's persistent 2-stage cp.async pipeline):
//  - epilogue sqrt via sqrt.approx.f32 (harness builds without fast-math; the
//    IEEE sqrtf sequence was ~9 ops x 64/thread and showed up as fma/alu 20%).
//  - fmaf(-2, cross, xs+es) folding.
//  - __stcs streaming stores (write-once output, keep L2 for X/E tiles).

#define BM 128
#define BN 128
#define MAXN 65536
#define MAXK 1024

// per-stage smem layout (bytes): A 0..16384, B 16384..32768, xs 32768..33280,
// es 33280..33792. stage size 33792 (128-aligned).
#define ST_B   16384
#define ST_XS  32768
#define ST_ES  33280
#define STAGE  33792
#define DYN_SMEM (2 * STAGE)

__device__ __nv_bfloat16 g_Xbf[MAXN * 64];
__device__ float         g_xsq[MAXN];
__device__ __nv_bfloat16 g_Ebf[MAXK * 64];
__device__ float         g_esq[MAXK];

#define SWZ(o) ((o) ^ (((o) >> 3) & 0x70))

__device__ __forceinline__ void ldsm_x4(uint32_t& r0, uint32_t& r1, uint32_t& r2, uint32_t& r3, uint32_t addr) {
    asm volatile("ldmatrix.sync.aligned.m8n8.x4.shared.b16 {%0,%1,%2,%3}, [%4];"
                 : "=r"(r0), "=r"(r1), "=r"(r2), "=r"(r3) : "r"(addr));
}

__device__ __forceinline__ void mma_bf16(float* c, const uint32_t* a, uint32_t b0, uint32_t b1) {
    asm volatile("mma.sync.aligned.m16n8k16.row.col.f32.bf16.bf16.f32 "
                 "{%0,%1,%2,%3}, {%4,%5,%6,%7}, {%8,%9}, {%0,%1,%2,%3};"
                 : "+f"(c[0]), "+f"(c[1]), "+f"(c[2]), "+f"(c[3])
                 : "r"(a[0]), "r"(a[1]), "r"(a[2]), "r"(a[3]), "r"(b0), "r"(b1));
}

__device__ __forceinline__ void cp16(uint32_t dst, const void* src) {
    asm volatile("cp.async.cg.shared.global [%0], [%1], 16;" :: "r"(dst), "l"(src) : "memory");
}

__device__ __forceinline__ float sqrt_approx(float x) {
    float r;
    asm("sqrt.approx.f32 %0, %1;" : "=f"(r) : "f"(x));
    return r;
}

// dist = sqrt(max(xs+es - 2*c, 0))
__device__ __forceinline__ float dist1(float xe, float c) {
    return sqrt_approx(fmaxf(fmaf(-2.0f, c, xe), 0.0f));
}

// logical col l (within 16-group) -> physical smem row, so that mma fragment
// ownership {2t, 2t+1, 2t+8, 2t+9} (phys) maps to logical {4t..4t+3}.
__device__ __forceinline__ int bperm(int l) {
    int t = l >> 2, j = l & 3;
    return 2 * t + (j & 1) + ((j >> 1) << 3);
}

// ---------------- merged prep: fp32 -> bf16 + exact fp32 row norms ----------------
__global__ __launch_bounds__(256)
void conv_all(const float* __restrict__ X, const float* __restrict__ E, int kblocks) {
    const int b    = blockIdx.x;
    const int tid  = threadIdx.x;
    const int lane = tid & 31;
    const float4* sv;
    __nv_bfloat16* drow;
    float* sqrow;
    if (b < kblocks) {
        sv    = reinterpret_cast<const float4*>(E) + (size_t)b * 2048;
        drow  = g_Ebf + (size_t)b * 8192;
        sqrow = g_esq + (size_t)b * 128;
    } else {
        const int c = b - kblocks;
        sv    = reinterpret_cast<const float4*>(X) + (size_t)c * 2048;
        drow  = g_Xbf + (size_t)c * 8192;
        sqrow = g_xsq + (size_t)c * 128;
    }
    #pragma unroll
    for (int i = 0; i < 8; i++) {
        const int f   = tid + i * 256;     // 2048 float4 per 128-row block
        const int row = f >> 4;
        const int c4  = f & 15;
        float4 v = sv[f];
        float ss = v.x * v.x + v.y * v.y + v.z * v.z + v.w * v.w;
        __nv_bfloat162 p0 = __floats2bfloat162_rn(v.x, v.y);
        __nv_bfloat162 p1 = __floats2bfloat162_rn(v.z, v.w);
        uint2 pk;
        pk.x = *reinterpret_cast<uint32_t*>(&p0);
        pk.y = *reinterpret_cast<uint32_t*>(&p1);
        *reinterpret_cast<uint2*>(drow + row * 64 + c4 * 4) = pk;
        ss += __shfl_xor_sync(0xffffffffu, ss, 1);
        ss += __shfl_xor_sync(0xffffffffu, ss, 2);
        ss += __shfl_xor_sync(0xffffffffu, ss, 4);
        ss += __shfl_xor_sync(0xffffffffu, ss, 8);
        if ((lane & 15) == 0) sqrow[row] = ss;
    }
}

// ---------------- main: persistent, 2-stage cp.async pipeline ----------------
__device__ __forceinline__ void issue_tile_loads(uint32_t stg_base, int m0, int n0, int tid) {
    const uint32_t a0 = stg_base;
    const uint32_t b0 = stg_base + ST_B;
    #pragma unroll
    for (int i = 0; i < 4; i++) {                  // A: 1024 chunks of 16B
        const int f   = tid + i * 256;
        const int row = f >> 3;
        const int c   = f & 7;
        cp16(a0 + SWZ((uint32_t)(row * 128 + c * 16)),
             g_Xbf + (size_t)(m0 + row) * 64 + c * 8);
    }
    #pragma unroll
    for (int i = 0; i < 4; i++) {                  // B: 1024 chunks, permuted rows
        const int f    = tid + i * 256;
        const int lrow = f >> 3;
        const int c    = f & 7;
        const int prow = (lrow & ~15) | bperm(lrow & 15);
        cp16(b0 + SWZ((uint32_t)(prow * 128 + c * 16)),
             g_Ebf + (size_t)(n0 + lrow) * 64 + c * 8);
    }
    if (tid < 32)       cp16(stg_base + ST_XS + tid * 16, g_xsq + m0 + tid * 4);
    else if (tid < 64)  cp16(stg_base + ST_ES + (tid - 32) * 16, g_esq + n0 + (tid - 32) * 4);
}

__global__ __launch_bounds__(256, 2)
void vq_cdist_kernel(float* __restrict__ out, int Kdim, int nt_total, int nx) {
    extern __shared__ char smem[];
    const uint32_t s_base = (uint32_t)__cvta_generic_to_shared(smem);

    const int tid  = threadIdx.x;
    const int lane = tid & 31;
    const int wid  = tid >> 5;
    const int wm = (wid & 3) * 32;
    const int wn = (wid >> 2) * 64;
    const int stride = gridDim.x;

    int t = blockIdx.x;
    if (t < nt_total) {
        issue_tile_loads(s_base, (t / nx) * BM, (t % nx) * BN, tid);
        asm volatile("cp.async.commit_group;" ::: "memory");
    }

    int pb = 0;
    for (; t < nt_total; t += stride, pb ^= 1) {
        const int tn = t + stride;
        if (tn < nt_total) {
            issue_tile_loads(s_base + (pb ^ 1) * STAGE, (tn / nx) * BM, (tn % nx) * BN, tid);
            asm volatile("cp.async.commit_group;" ::: "memory");
            asm volatile("cp.async.wait_group 1;" ::: "memory");
        } else {
            asm volatile("cp.async.wait_group 0;" ::: "memory");
        }
        __syncthreads();

        const uint32_t a_base = s_base + pb * STAGE;
        const uint32_t b_base = a_base + ST_B;
        const float* xs_s = reinterpret_cast<const float*>(smem + pb * STAGE + ST_XS);
        const float* es_s = reinterpret_cast<const float*>(smem + pb * STAGE + ST_ES);
        const int m0 = (t / nx) * BM;
        const int n0 = (t % nx) * BN;

        float acc[2][8][4];
        #pragma unroll
        for (int mt = 0; mt < 2; mt++)
            #pragma unroll
            for (int nt2 = 0; nt2 < 8; nt2++)
                #pragma unroll
                for (int i = 0; i < 4; i++) acc[mt][nt2][i] = 0.f;

        #pragma unroll
        for (int ks = 0; ks < 4; ks++) {
            const int kc = ks * 16;

            uint32_t a_frag[2][4];
            #pragma unroll
            for (int mt = 0; mt < 2; mt++) {
                const int r  = wm + mt * 16 + (lane & 15);
                const int cb = (kc + ((lane >> 4) << 3)) * 2;
                ldsm_x4(a_frag[mt][0], a_frag[mt][1], a_frag[mt][2], a_frag[mt][3],
                        a_base + SWZ((uint32_t)(r * 128 + cb)));
            }

            #pragma unroll
            for (int np = 0; np < 4; np++) {
                const int nr = wn + np * 16 + ((lane >> 4) & 1) * 8 + (lane & 7);
                const int kb = (kc + ((lane >> 3) & 1) * 8) * 2;
                uint32_t r0, r1, r2, r3;
                ldsm_x4(r0, r1, r2, r3, b_base + SWZ((uint32_t)(nr * 128 + kb)));
                #pragma unroll
                for (int mt = 0; mt < 2; mt++) {
                    mma_bf16(acc[mt][np * 2],     a_frag[mt], r0, r1);
                    mma_bf16(acc[mt][np * 2 + 1], a_frag[mt], r2, r3);
                }
            }
        }

        // epilogue: thread owns 4 contiguous logical cols per 16-group
        const int rb = wm + (lane >> 2);
        const int t4 = (lane & 3) * 4;
        #pragma unroll
        for (int mt = 0; mt < 2; mt++) {
            const int lr0 = rb + mt * 16;
            const int lr1 = lr0 + 8;
            const float xsa = xs_s[lr0];
            const float xsb = xs_s[lr1];
            float* o0 = out + (size_t)(m0 + lr0) * Kdim + n0 + wn;
            float* o1 = out + (size_t)(m0 + lr1) * Kdim + n0 + wn;
            #pragma unroll
            for (int q = 0; q < 4; q++) {
                const int c = q * 16 + t4;
                const float4 es = *reinterpret_cast<const float4*>(&es_s[wn + c]);
                float4 v0, v1;
                v0.x = dist1(xsa + es.x, acc[mt][2*q][0]);
                v0.y = dist1(xsa + es.y, acc[mt][2*q][1]);
                v0.z = dist1(xsa + es.z, acc[mt][2*q+1][0]);
                v0.w = dist1(xsa + es.w, acc[mt][2*q+1][1]);
                v1.x = dist1(xsb + es.x, acc[mt][2*q][2]);
                v1.y = dist1(xsb + es.y, acc[mt][2*q][3]);
                v1.z = dist1(xsb + es.z, acc[mt][2*q+1][2]);
                v1.w = dist1(xsb + es.w, acc[mt][2*q+1][3]);
                __stcs(reinterpret_cast<float4*>(o0 + c), v0);
                __stcs(reinterpret_cast<float4*>(o1 + c), v1);
            }
        }
        __syncthreads();   // all reads of stage pb done before next prefetch overwrites it
    }
}

extern "C" void kernel_launch(void* const* d_in, const int* in_sizes, int n_in,
                              void* d_out, int out_size) {
    const float* X = (const float*)d_in[0];   // inputs [N, 64]
    const float* E = (const float*)d_in[1];   // embeddings [K, 64]
    float* out = (float*)d_out;               // [N, K] fp32

    const int N = in_sizes[0] / 64;
    const int K = in_sizes[1] / 64;
    const int nx = K / BN;
    const int nt_total = (N / BM) * nx;

    static int configured = 0;
    if (!configured) {
        cudaFuncSetAttribute(vq_cdist_kernel,
                             cudaFuncAttributeMaxDynamicSharedMemorySize, DYN_SMEM);
        configured = 1;
    }

    int sms = 148;
    cudaDeviceGetAttribute(&sms, cudaDevAttrMultiProcessorCount, 0);

    conv_all<<<K / 128 + N / 128, 256>>>(X, E, K / 128);
    vq_cdist_kernel<<<2 * sms, 256, DYN_SMEM>>>(out, K, nt_total, nx);
}

// round 10
// speedup vs baseline: 1.8272x; 1.0328x over previous
#include <cuda_runtime.h>
#include <cuda_bf16.h>
#include <cstdint>

// VQ cdist: out[n,k] = sqrt(max(||x_n||^2 + ||e_k||^2 - 2 x_n.e_k, 0))
// N=65536, K=1024, D=64.  mma.sync path (tcgen05 rejected by compute_103).
//
// R10 = R9 with the B-fragment fix: persistent B fragment build must include
// the warp's wn offset (R9 dropped it -> warps with wn=32 read rows 0..31,
// rel_err 6.3e-3). Design: CTA pinned to one 64-col n-tile; B fragments built
// ONCE into registers and reused across ~27 m-tiles (per-tile LDSM A-only);
// 3-stage cp.async pipeline on A; sqrt.approx + __stcs epilogue.

#define BM 128
#define BN 64

// smem layout: 3 A-stages (A 16KB + xs 512B each), then B 8KB, then es 256B
#define ST_XS  16384
#define STAGE  16896
#define B_OFF  (3 * STAGE)          // 50688
#define ES_OFF (B_OFF + 8192)       // 58880
#define DYN_SMEM (ES_OFF + 256)     // 59136

#define MAXN 65536
#define MAXK 1024

__device__ __nv_bfloat16 g_Xbf[MAXN * 64];
__device__ float         g_xsq[MAXN];
__device__ __nv_bfloat16 g_Ebf[MAXK * 64];
__device__ float         g_esq[MAXK];

#define SWZ(o) ((o) ^ (((o) >> 3) & 0x70))

__device__ __forceinline__ void ldsm_x4(uint32_t& r0, uint32_t& r1, uint32_t& r2, uint32_t& r3, uint32_t addr) {
    asm volatile("ldmatrix.sync.aligned.m8n8.x4.shared.b16 {%0,%1,%2,%3}, [%4];"
                 : "=r"(r0), "=r"(r1), "=r"(r2), "=r"(r3) : "r"(addr));
}

__device__ __forceinline__ void mma_bf16(float* c, const uint32_t* a, uint32_t b0, uint32_t b1) {
    asm volatile("mma.sync.aligned.m16n8k16.row.col.f32.bf16.bf16.f32 "
                 "{%0,%1,%2,%3}, {%4,%5,%6,%7}, {%8,%9}, {%0,%1,%2,%3};"
                 : "+f"(c[0]), "+f"(c[1]), "+f"(c[2]), "+f"(c[3])
                 : "r"(a[0]), "r"(a[1]), "r"(a[2]), "r"(a[3]), "r"(b0), "r"(b1));
}

__device__ __forceinline__ void cp16(uint32_t dst, const void* src) {
    asm volatile("cp.async.cg.shared.global [%0], [%1], 16;" :: "r"(dst), "l"(src) : "memory");
}

__device__ __forceinline__ float sqrt_approx(float x) {
    float r;
    asm("sqrt.approx.f32 %0, %1;" : "=f"(r) : "f"(x));
    return r;
}
__device__ __forceinline__ float dist1(float xe, float c) {
    return sqrt_approx(fmaxf(fmaf(-2.0f, c, xe), 0.0f));
}

// logical col l (within 16-group) -> physical smem row, so that mma fragment
// ownership {2t, 2t+1, 2t+8, 2t+9} (phys) maps to logical {4t..4t+3}.
__device__ __forceinline__ int bperm(int l) {
    int t = l >> 2, j = l & 3;
    return 2 * t + (j & 1) + ((j >> 1) << 3);
}

// ---------------- merged prep: fp32 -> bf16 + exact fp32 row norms ----------------
__global__ __launch_bounds__(256)
void conv_all(const float* __restrict__ X, const float* __restrict__ E, int kblocks) {
    const int b    = blockIdx.x;
    const int tid  = threadIdx.x;
    const int lane = tid & 31;
    const float4* sv;
    __nv_bfloat16* drow;
    float* sqrow;
    if (b < kblocks) {
        sv    = reinterpret_cast<const float4*>(E) + (size_t)b * 2048;
        drow  = g_Ebf + (size_t)b * 8192;
        sqrow = g_esq + (size_t)b * 128;
    } else {
        const int c = b - kblocks;
        sv    = reinterpret_cast<const float4*>(X) + (size_t)c * 2048;
        drow  = g_Xbf + (size_t)c * 8192;
        sqrow = g_xsq + (size_t)c * 128;
    }
    #pragma unroll
    for (int i = 0; i < 8; i++) {
        const int f   = tid + i * 256;
        const int row = f >> 4;
        const int c4  = f & 15;
        float4 v = sv[f];
        float ss = v.x * v.x + v.y * v.y + v.z * v.z + v.w * v.w;
        __nv_bfloat162 p0 = __floats2bfloat162_rn(v.x, v.y);
        __nv_bfloat162 p1 = __floats2bfloat162_rn(v.z, v.w);
        uint2 pk;
        pk.x = *reinterpret_cast<uint32_t*>(&p0);
        pk.y = *reinterpret_cast<uint32_t*>(&p1);
        *reinterpret_cast<uint2*>(drow + row * 64 + c4 * 4) = pk;
        ss += __shfl_xor_sync(0xffffffffu, ss, 1);
        ss += __shfl_xor_sync(0xffffffffu, ss, 2);
        ss += __shfl_xor_sync(0xffffffffu, ss, 4);
        ss += __shfl_xor_sync(0xffffffffu, ss, 8);
        if ((lane & 15) == 0) sqrow[row] = ss;
    }
}

// ---------------- main ----------------
__device__ __forceinline__ void issue_A(uint32_t stg, int m0, int tid) {
    #pragma unroll
    for (int i = 0; i < 4; i++) {                  // 1024 chunks of 16B
        const int f   = tid + i * 256;
        const int row = f >> 3;
        const int c   = f & 7;
        cp16(stg + SWZ((uint32_t)(row * 128 + c * 16)),
             g_Xbf + (size_t)(m0 + row) * 64 + c * 8);
    }
    if (tid < 32) cp16(stg + ST_XS + tid * 16, g_xsq + m0 + tid * 4);
}

__global__ __launch_bounds__(256, 2)
void vq_cdist_kernel(float* __restrict__ out, int Kdim, int nm, int nx) {
    extern __shared__ char smem[];
    const uint32_t s_base = (uint32_t)__cvta_generic_to_shared(smem);

    const int tid  = threadIdx.x;
    const int lane = tid & 31;
    const int wid  = tid >> 5;
    const int wm = (wid & 3) * 32;
    const int wn = (wid >> 2) * 32;

    const int group = blockIdx.x / nx;          // m-stripe group
    const int n0    = (blockIdx.x % nx) * BN;   // fixed n-tile for this CTA
    const int ng    = gridDim.x / nx;

    // ---- prologue: B tile + es (once), then first two A stages ----
    {
        const uint32_t b0 = s_base + B_OFF;
        #pragma unroll
        for (int i = 0; i < 2; i++) {              // 512 chunks (64 rows x 128B)
            const int f    = tid + i * 256;
            const int lrow = f >> 3;
            const int c    = f & 7;
            const int prow = (lrow & ~15) | bperm(lrow & 15);
            cp16(b0 + SWZ((uint32_t)(prow * 128 + c * 16)),
                 g_Ebf + (size_t)(n0 + lrow) * 64 + c * 8);
        }
        if (tid < 16) cp16(s_base + ES_OFF + tid * 16, g_esq + n0 + tid * 4);
        asm volatile("cp.async.commit_group;" ::: "memory");
    }
    issue_A(s_base, group * BM, tid);
    asm volatile("cp.async.commit_group;" ::: "memory");
    issue_A(s_base + STAGE, (group + ng) * BM, tid);   // every group has >= 2 tiles
    asm volatile("cp.async.commit_group;" ::: "memory");

    asm volatile("cp.async.wait_group 2;" ::: "memory");   // B + es complete
    __syncthreads();

    // ---- build persistent B fragments (32 regs) — includes wn (R9 bug fix) ----
    uint32_t bfr[4][2][4];
    #pragma unroll
    for (int ks = 0; ks < 4; ks++) {
        #pragma unroll
        for (int np = 0; np < 2; np++) {
            const int nr = wn + np * 16 + ((lane >> 4) & 1) * 8 + (lane & 7);
            const int kb = (ks * 16 + ((lane >> 3) & 1) * 8) * 2;
            ldsm_x4(bfr[ks][np][0], bfr[ks][np][1], bfr[ks][np][2], bfr[ks][np][3],
                    s_base + B_OFF + SWZ((uint32_t)(nr * 128 + kb)));
        }
    }
    const float* es_s = reinterpret_cast<const float*>(smem + ES_OFF);

    // ---- main loop over m-tiles, 3-stage pipeline ----
    int st = 0;
    for (int mi = group; mi < nm; mi += ng) {
        const int mi2 = mi + 2 * ng;
        if (mi2 < nm) {
            const int st2 = (st == 0) ? 2 : st - 1;   // (st+2) % 3
            issue_A(s_base + st2 * STAGE, mi2 * BM, tid);
            asm volatile("cp.async.commit_group;" ::: "memory");
            asm volatile("cp.async.wait_group 2;" ::: "memory");
        } else if (mi + ng < nm) {
            asm volatile("cp.async.wait_group 1;" ::: "memory");
        } else {
            asm volatile("cp.async.wait_group 0;" ::: "memory");
        }
        __syncthreads();

        const uint32_t a_base = s_base + st * STAGE;
        const float* xs_s = reinterpret_cast<const float*>(smem + st * STAGE + ST_XS);
        const int m0 = mi * BM;

        float acc[2][4][4];
        #pragma unroll
        for (int mt = 0; mt < 2; mt++)
            #pragma unroll
            for (int nt = 0; nt < 4; nt++)
                #pragma unroll
                for (int i = 0; i < 4; i++) acc[mt][nt][i] = 0.f;

        #pragma unroll
        for (int ks = 0; ks < 4; ks++) {
            const int kc = ks * 16;
            uint32_t a_frag[2][4];
            #pragma unroll
            for (int mt = 0; mt < 2; mt++) {
                const int r  = wm + mt * 16 + (lane & 15);
                const int cb = (kc + ((lane >> 4) << 3)) * 2;
                ldsm_x4(a_frag[mt][0], a_frag[mt][1], a_frag[mt][2], a_frag[mt][3],
                        a_base + SWZ((uint32_t)(r * 128 + cb)));
            }
            #pragma unroll
            for (int np = 0; np < 2; np++) {
                #pragma unroll
                for (int mt = 0; mt < 2; mt++) {
                    mma_bf16(acc[mt][np * 2],     a_frag[mt], bfr[ks][np][0], bfr[ks][np][1]);
                    mma_bf16(acc[mt][np * 2 + 1], a_frag[mt], bfr[ks][np][2], bfr[ks][np][3]);
                }
            }
        }

        // ---- epilogue: thread owns 4 contiguous logical cols per 16-group ----
        const int rb = wm + (lane >> 2);
        const int t4 = (lane & 3) * 4;
        #pragma unroll
        for (int mt = 0; mt < 2; mt++) {
            const int lr0 = rb + mt * 16;
            const int lr1 = lr0 + 8;
            const float xsa = xs_s[lr0];
            const float xsb = xs_s[lr1];
            float* o0 = out + (size_t)(m0 + lr0) * Kdim + n0 + wn;
            float* o1 = out + (size_t)(m0 + lr1) * Kdim + n0 + wn;
            #pragma unroll
            for (int q = 0; q < 2; q++) {
                const int c = q * 16 + t4;
                const float4 es = *reinterpret_cast<const float4*>(&es_s[wn + c]);
                float4 v0, v1;
                v0.x = dist1(xsa + es.x, acc[mt][2*q][0]);
                v0.y = dist1(xsa + es.y, acc[mt][2*q][1]);
                v0.z = dist1(xsa + es.z, acc[mt][2*q+1][0]);
                v0.w = dist1(xsa + es.w, acc[mt][2*q+1][1]);
                v1.x = dist1(xsb + es.x, acc[mt][2*q][2]);
                v1.y = dist1(xsb + es.y, acc[mt][2*q][3]);
                v1.z = dist1(xsb + es.z, acc[mt][2*q+1][2]);
                v1.w = dist1(xsb + es.w, acc[mt][2*q+1][3]);
                __stcs(reinterpret_cast<float4*>(o0 + c), v0);
                __stcs(reinterpret_cast<float4*>(o1 + c), v1);
            }
        }
        __syncthreads();   // reads of stage st done before it is refilled

        st = (st == 2) ? 0 : st + 1;
    }
}

extern "C" void kernel_launch(void* const* d_in, const int* in_sizes, int n_in,
                              void* d_out, int out_size) {
    const float* X = (const float*)d_in[0];   // inputs [N, 64]
    const float* E = (const float*)d_in[1];   // embeddings [K, 64]
    float* out = (float*)d_out;               // [N, K] fp32

    const int N = in_sizes[0] / 64;
    const int K = in_sizes[1] / 64;
    const int nx = K / BN;                    // 16
    const int nm = N / BM;                    // 512

    static int configured = 0;
    if (!configured) {
        cudaFuncSetAttribute(vq_cdist_kernel,
                             cudaFuncAttributeMaxDynamicSharedMemorySize, DYN_SMEM);
        configured = 1;
    }

    int sms = 148;
    cudaDeviceGetAttribute(&sms, cudaDevAttrMultiProcessorCount, 0);
    int grid = (2 * sms / nx) * nx;           // multiple of nx (304 on GB300)
    if (grid < nx) grid = nx;

    conv_all<<<K / 128 + N / 128, 256>>>(X, E, K / 128);
    vq_cdist_kernel<<<grid, 256, DYN_SMEM>>>(out, K, nm, nx);
}